// round 2
// baseline (speedup 1.0000x reference)
#include <cuda_runtime.h>
#include <cstdint>

// CRF NLL: out[b] = log_Z(b) - gold(b)
// B=1024, T=512, L=64. START=0, STOP=1, NEG=-10000.

#define Bn 1024
#define Tn 512
#define Ln 64
#define LN2F 0.6931471805599453f

__device__ float g_gold[Bn];

// ---- packed f32x2 helpers (Blackwell FFMA2 path) ----
__device__ __forceinline__ unsigned long long pk2(float x, float y) {
    unsigned long long r;
    asm("mov.b64 %0, {%1, %2};" : "=l"(r) : "f"(x), "f"(y));
    return r;
}
__device__ __forceinline__ void unpk2(unsigned long long v, float& x, float& y) {
    asm("mov.b64 {%0, %1}, %2;" : "=f"(x), "=f"(y) : "l"(v));
}
__device__ __forceinline__ unsigned long long fma2(unsigned long long a,
                                                   unsigned long long b,
                                                   unsigned long long c) {
    unsigned long long d;
    asm("fma.rn.f32x2 %0, %1, %2, %3;" : "=l"(d) : "l"(a), "l"(b), "l"(c));
    return d;
}
__device__ __forceinline__ unsigned long long add2(unsigned long long a,
                                                   unsigned long long b) {
    unsigned long long d;
    asm("add.rn.f32x2 %0, %1, %2;" : "=l"(d) : "l"(a), "l"(b));
    return d;
}

// ============================================================================
// Gold score: sum_t ( T[cur_t, prev_t] + feats[b, t, cur_t] ), t = 1..511
// Runtime-detects int64 vs int32 label storage.
// ============================================================================
__global__ void crf_gold_kernel(const float* __restrict__ feats,
                                const float* __restrict__ trans,
                                const int*   __restrict__ labels32) {
    const int b   = blockIdx.x;
    const int tid = threadIdx.x;   // 256 threads

    // int64 detection: small nonneg labels stored as int64 (LE) have every
    // odd 32-bit word == 0. Check 32 words total (front and back).
    // False-positive probability with int32 labels in [0,64): (1/2^32-ish)^32 ~ 0.
    int stride = 2;
    #pragma unroll
    for (int k = 0; k < 16; k++) {
        if (labels32[2 * k + 1] != 0) stride = 1;
        if (labels32[2 * (Bn * Tn / 2 - 1 - k) + 1] != 0) stride = 1;
    }

    float acc = 0.0f;
    const long long lbase = (long long)b * Tn;
    const long long fbase = (long long)b * Tn * Ln;
    for (int t = 1 + tid; t < Tn; t += 256) {
        int cur  = labels32[(lbase + t) * stride];
        int prev = labels32[(lbase + t - 1) * stride];
        acc += __ldg(trans + cur * Ln + prev) + __ldg(feats + fbase + t * Ln + cur);
    }

    // block reduce (8 warps)
    #pragma unroll
    for (int off = 16; off; off >>= 1)
        acc += __shfl_xor_sync(0xffffffffu, acc, off);
    __shared__ float red[8];
    const int wid  = tid >> 5;
    const int lane = tid & 31;
    if (lane == 0) red[wid] = acc;
    __syncthreads();
    if (tid == 0) {
        float s = 0.0f;
        #pragma unroll
        for (int w = 0; w < 8; w++) s += red[w];
        g_gold[b] = s;
    }
}

// ============================================================================
// Forward algorithm. One block (64 threads) per batch; thread i owns label i.
// State: s_i = exp(a_i - M) in register; per-step 64x64 matvec with E-row in
// registers (packed f32x2) reading broadcast s from smem; one barrier/step.
// Normalizer delta is a lag-1, exponent-bits-only estimate published by
// thread 32 (self-correcting; cross-label spread of a is bounded, so fp32
// scaled probabilities never harmfully over/underflow).
// ============================================================================
__global__ __launch_bounds__(64, 8)
void crf_forward_kernel(const float* __restrict__ feats,
                        const float* __restrict__ trans,
                        float* __restrict__ out) {
    const int b = blockIdx.x;
    const int i = threadIdx.x;   // label 0..63

    __shared__ __align__(16) float sh_s[2][Ln];
    __shared__ float sh_delta[2];
    __shared__ float sh_red[2];

    // ---- load E row i = exp(trans[i, :]) packed as 32 x f32x2 registers ----
    unsigned long long E2[32];
    {
        const float2* trow = reinterpret_cast<const float2*>(trans + i * Ln);
        #pragma unroll
        for (int k = 0; k < 32; k++) {
            float2 tv = __ldg(trow + k);
            float e0 = (tv.x < -80.0f) ? 0.0f : __expf(tv.x);
            float e1 = (tv.y < -80.0f) ? 0.0f : __expf(tv.y);
            E2[k] = pk2(e0, e1);
        }
    }

    // ---- init: a_0[j] = (j==START) ? 0 : NEG  ->  s one-hot, M = 0 ----
    sh_s[0][i] = (i == 0) ? 1.0f : 0.0f;
    if (i == 0) sh_delta[0] = 0.0f;
    float M = 0.0f;
    __syncthreads();

    const long long fbase = (long long)b * Tn * Ln;
    float f = __ldg(feats + fbase + 1 * Ln + i);   // feat for t=1
    float sn = 0.0f;
    int cur = 0;

    for (int t = 1; t < Tn; ++t) {
        const int nxt = cur ^ 1;

        // prefetch next step's feature (clamped at the end; redundant safe load)
        const int tp = (t + 1 < Tn) ? (t + 1) : (Tn - 1);
        float f_next = __ldg(feats + fbase + tp * Ln + i);

        // ---- matvec q_i = sum_j E[i][j] * s[j] (packed, 4 accumulators) ----
        const float4* pv = reinterpret_cast<const float4*>(sh_s[cur]);
        unsigned long long a0 = 0ull, a1 = 0ull, a2 = 0ull, a3 = 0ull;
        #pragma unroll
        for (int k = 0; k < 16; k += 2) {
            float4 v0 = pv[k];
            float4 v1 = pv[k + 1];
            a0 = fma2(E2[2 * k + 0], pk2(v0.x, v0.y), a0);
            a1 = fma2(E2[2 * k + 1], pk2(v0.z, v0.w), a1);
            a2 = fma2(E2[2 * k + 2], pk2(v1.x, v1.y), a2);
            a3 = fma2(E2[2 * k + 3], pk2(v1.z, v1.w), a3);
        }
        unsigned long long asum = add2(add2(a0, a1), add2(a2, a3));
        float qlo, qhi;
        unpk2(asum, qlo, qhi);
        const float q = qlo + qhi;

        // ---- rescale: s' = q * exp(f - delta), M += delta ----
        const float delta = sh_delta[cur];
        sn = q * __expf(f - delta);
        M += delta;

        // designated thread publishes next delta ~ log(s'_ref) via exponent bits
        if (i == 32) {
            int e = ((__float_as_int(sn) >> 23) & 0xFF) - 127;
            if (e < -43) e = -43;   // safety clamp
            if (e >  43) e =  43;
            sh_delta[nxt] = (float)e * LN2F;
        }
        sh_s[nxt][i] = sn;

        f = f_next;
        cur = nxt;
        __syncthreads();
    }

    // ---- log_Z = M + log(sum_i s_i);  out = log_Z - gold ----
    float v = sn;
    #pragma unroll
    for (int off = 16; off; off >>= 1)
        v += __shfl_xor_sync(0xffffffffu, v, off);
    if ((i & 31) == 0) sh_red[i >> 5] = v;
    __syncthreads();
    if (i == 0) {
        float total = sh_red[0] + sh_red[1];
        out[b] = M + logf(total) - g_gold[b];
    }
}

// ============================================================================
// Launch
// ============================================================================
extern "C" void kernel_launch(void* const* d_in, const int* in_sizes, int n_in,
                              void* d_out, int out_size) {
    const float* feats  = (const float*)d_in[0];   // [B, T, L] f32
    const float* trans  = (const float*)d_in[1];   // [L, L]    f32
    const int*   labels = (const int*)  d_in[2];   // [B, T]    int (32 or 64, detected)
    float* out = (float*)d_out;                    // [B] f32

    crf_gold_kernel<<<Bn, 256>>>(feats, trans, labels);
    crf_forward_kernel<<<Bn, Ln>>>(feats, trans, out);
}

// round 5
// speedup vs baseline: 1.1285x; 1.1285x over previous
#include <cuda_runtime.h>
#include <cstdint>

// CRF NLL: out[b] = log_Z(b) - gold(b)
// B=1024, T=512, L=64. START=0, STOP=1, NEG=-10000.

#define Bn 1024
#define Tn 512
#define Ln 64
#define LN2F 0.6931471805599453f

__device__ float g_gold[Bn];

// ---- packed f32x2 helpers (Blackwell FFMA2 path) ----
__device__ __forceinline__ unsigned long long fma2(unsigned long long a,
                                                   unsigned long long b,
                                                   unsigned long long c) {
    unsigned long long d;
    asm("fma.rn.f32x2 %0, %1, %2, %3;" : "=l"(d) : "l"(a), "l"(b), "l"(c));
    return d;
}
__device__ __forceinline__ unsigned long long add2(unsigned long long a,
                                                   unsigned long long b) {
    unsigned long long d;
    asm("add.rn.f32x2 %0, %1, %2;" : "=l"(d) : "l"(a), "l"(b));
    return d;
}
__device__ __forceinline__ unsigned long long pk2(float x, float y) {
    unsigned long long r;
    asm("mov.b64 %0, {%1, %2};" : "=l"(r) : "f"(x), "f"(y));
    return r;
}
__device__ __forceinline__ void unpk2(unsigned long long v, float& x, float& y) {
    asm("mov.b64 {%0, %1}, %2;" : "=f"(x), "=f"(y) : "l"(v));
}

// ============================================================================
// Gold score: sum_t ( T[cur_t, prev_t] + feats[b, t, cur_t] ), t = 1..511
// Runtime-detects int64 vs int32 label storage.
// ============================================================================
__global__ void crf_gold_kernel(const float* __restrict__ feats,
                                const float* __restrict__ trans,
                                const int*   __restrict__ labels32) {
    const int b   = blockIdx.x;
    const int tid = threadIdx.x;   // 256 threads

    // int64 detection: small nonneg labels stored as int64 (LE) have every
    // odd 32-bit word == 0. Check 32 words (front and back).
    int stride = 2;
    #pragma unroll
    for (int k = 0; k < 16; k++) {
        if (labels32[2 * k + 1] != 0) stride = 1;
        if (labels32[2 * (Bn * Tn / 2 - 1 - k) + 1] != 0) stride = 1;
    }

    float acc = 0.0f;
    const long long lbase = (long long)b * Tn;
    const long long fbase = (long long)b * Tn * Ln;
    for (int t = 1 + tid; t < Tn; t += 256) {
        int cur  = labels32[(lbase + t) * stride];
        int prev = labels32[(lbase + t - 1) * stride];
        acc += __ldg(trans + cur * Ln + prev) + __ldg(feats + fbase + t * Ln + cur);
    }

    #pragma unroll
    for (int off = 16; off; off >>= 1)
        acc += __shfl_xor_sync(0xffffffffu, acc, off);
    __shared__ float red[8];
    const int wid  = tid >> 5;
    const int lane = tid & 31;
    if (lane == 0) red[wid] = acc;
    __syncthreads();
    if (tid == 0) {
        float s = 0.0f;
        #pragma unroll
        for (int w = 0; w < 8; w++) s += red[w];
        g_gold[b] = s;
    }
}

// ============================================================================
// Forward algorithm. One block (64 threads) per batch; thread i owns label i.
// s_j = exp(a_j - M) broadcast via double-buffered smem; E row in 32 packed
// f32x2 registers; one barrier per step.
// vs R2 (235us, latency-bound on depth-1 feat prefetch):
//  - feats prefetched 4 steps deep (4-reg circular buffer, static unroll) to
//    cover the ~600-800 cyc DRAM latency that pinned step time at ~850 cyc.
//  - s operands loaded as LDS.64 packed pairs (no pack MOVs).
// ============================================================================
__global__ __launch_bounds__(64, 8)
void crf_forward_kernel(const float* __restrict__ feats,
                        const float* __restrict__ trans,
                        float* __restrict__ out) {
    const int b = blockIdx.x;
    const int i = threadIdx.x;   // label 0..63

    __shared__ __align__(16) float sh_s[2][Ln];
    __shared__ float sh_delta[2];
    __shared__ float sh_red[2];

    // ---- E row i = exp(trans[i, :]) as 32 packed f32x2 registers ----
    unsigned long long E2[32];
    {
        const float2* trow = reinterpret_cast<const float2*>(trans + i * Ln);
        #pragma unroll
        for (int k = 0; k < 32; k++) {
            float2 tv = __ldg(trow + k);
            float e0 = (tv.x < -80.0f) ? 0.0f : __expf(tv.x);
            float e1 = (tv.y < -80.0f) ? 0.0f : __expf(tv.y);
            E2[k] = pk2(e0, e1);
        }
    }

    // ---- init: s one-hot at START, M = 0 ----
    sh_s[0][i] = (i == 0) ? 1.0f : 0.0f;
    if (i == 0) sh_delta[0] = 0.0f;
    float M = 0.0f;
    __syncthreads();

    const float* fp = feats + (long long)b * Tn * Ln + i;

    // ---- prefetch pipeline: step k consumes feat t=k+1; depth 4 ----
    float fb0 = __ldg(fp + 1 * Ln);
    float fb1 = __ldg(fp + 2 * Ln);
    float fb2 = __ldg(fp + 3 * Ln);
    float fb3 = __ldg(fp + 4 * Ln);

    float sn = 0.0f;

    // One forward step. CUR/NXT are compile-time 0/1. FB holds feat for this
    // step and is refilled with feat for t=TPF (clamped; redundant loads at
    // the tail are harmless and stay in-bounds).
    #define STEP(FB, CUR, NXT, TPF)                                          \
    {                                                                        \
        const float f_use = FB;                                              \
        const int tpf = ((TPF) < Tn) ? (TPF) : (Tn - 1);                     \
        FB = __ldg(fp + (long long)tpf * Ln);                                \
        const float delta = sh_delta[CUR];                                   \
        const unsigned long long* pv =                                       \
            reinterpret_cast<const unsigned long long*>(sh_s[CUR]);          \
        unsigned long long a0 = 0ull, a1 = 0ull, a2 = 0ull, a3 = 0ull;       \
        _Pragma("unroll")                                                    \
        for (int k = 0; k < 32; k += 4) {                                    \
            a0 = fma2(E2[k + 0], pv[k + 0], a0);                             \
            a1 = fma2(E2[k + 1], pv[k + 1], a1);                             \
            a2 = fma2(E2[k + 2], pv[k + 2], a2);                             \
            a3 = fma2(E2[k + 3], pv[k + 3], a3);                             \
        }                                                                    \
        unsigned long long asum = add2(add2(a0, a1), add2(a2, a3));          \
        float qlo, qhi;                                                      \
        unpk2(asum, qlo, qhi);                                               \
        const float q = qlo + qhi;                                           \
        sn = q * __expf(f_use - delta);                                      \
        M += delta;                                                          \
        int e = ((__float_as_int(sn) >> 23) & 0xFF) - 127;                   \
        e = (e < -43) ? -43 : ((e > 43) ? 43 : e);                           \
        if (i == 32) sh_delta[NXT] = (float)e * LN2F;                        \
        sh_s[NXT][i] = sn;                                                   \
        __syncthreads();                                                     \
    }

    // 511 steps total: k = 0..510 (t = 1..511).
    // Main loop: 127 iterations x 4 steps = k 0..507.
    #pragma unroll 1
    for (int m = 0; m < 127; ++m) {
        const int k = 4 * m;
        STEP(fb0, 0, 1, k + 5);
        STEP(fb1, 1, 0, k + 6);
        STEP(fb2, 0, 1, k + 7);
        STEP(fb3, 1, 0, k + 8);
    }
    // Epilogue: k = 508, 509, 510.
    STEP(fb0, 0, 1, Tn - 1);
    STEP(fb1, 1, 0, Tn - 1);
    STEP(fb2, 0, 1, Tn - 1);

    #undef STEP

    // ---- log_Z = M + log(sum_i s_i);  out = log_Z - gold ----
    float v = sn;
    #pragma unroll
    for (int off = 16; off; off >>= 1)
        v += __shfl_xor_sync(0xffffffffu, v, off);
    if ((i & 31) == 0) sh_red[i >> 5] = v;
    __syncthreads();
    if (i == 0) {
        float total = sh_red[0] + sh_red[1];
        out[b] = M + logf(total) - g_gold[b];
    }
}

// ============================================================================
// Launch
// ============================================================================
extern "C" void kernel_launch(void* const* d_in, const int* in_sizes, int n_in,
                              void* d_out, int out_size) {
    const float* feats  = (const float*)d_in[0];   // [B, T, L] f32
    const float* trans  = (const float*)d_in[1];   // [L, L]    f32
    const int*   labels = (const int*)  d_in[2];   // [B, T]    int (32/64 detected)
    float* out = (float*)d_out;                    // [B] f32

    crf_gold_kernel<<<Bn, 256>>>(feats, trans, labels);
    crf_forward_kernel<<<Bn, Ln>>>(feats, trans, out);
}

// round 6
// speedup vs baseline: 1.1349x; 1.0057x over previous
#include <cuda_runtime.h>
#include <cstdint>

// CRF NLL: out[b] = log_Z(b) - gold(b)
// B=1024, T=512, L=64. START=0, STOP=1, NEG=-10000.

#define Bn 1024
#define Tn 512
#define Ln 64
#define LN2F 0.6931471805599453f

__device__ float g_gold[Bn];

// ---- packed f32x2 helpers (Blackwell FFMA2 path) ----
__device__ __forceinline__ unsigned long long fma2(unsigned long long a,
                                                   unsigned long long b,
                                                   unsigned long long c) {
    unsigned long long d;
    asm("fma.rn.f32x2 %0, %1, %2, %3;" : "=l"(d) : "l"(a), "l"(b), "l"(c));
    return d;
}
__device__ __forceinline__ unsigned long long add2(unsigned long long a,
                                                   unsigned long long b) {
    unsigned long long d;
    asm("add.rn.f32x2 %0, %1, %2;" : "=l"(d) : "l"(a), "l"(b));
    return d;
}
__device__ __forceinline__ unsigned long long pk2(float x, float y) {
    unsigned long long r;
    asm("mov.b64 %0, {%1, %2};" : "=l"(r) : "f"(x), "f"(y));
    return r;
}
__device__ __forceinline__ void unpk2(unsigned long long v, float& x, float& y) {
    asm("mov.b64 {%0, %1}, %2;" : "=f"(x), "=f"(y) : "l"(v));
}

// ============================================================================
// Gold score: sum_t ( T[cur_t, prev_t] + feats[b, t, cur_t] ), t = 1..511
// Runtime-detects int64 vs int32 label storage.
// ============================================================================
__global__ void crf_gold_kernel(const float* __restrict__ feats,
                                const float* __restrict__ trans,
                                const int*   __restrict__ labels32) {
    const int b   = blockIdx.x;
    const int tid = threadIdx.x;   // 256 threads

    // int64 detection: small nonneg labels stored as int64 (LE) have every
    // odd 32-bit word == 0. Check 32 words (front and back).
    int stride = 2;
    #pragma unroll
    for (int k = 0; k < 16; k++) {
        if (labels32[2 * k + 1] != 0) stride = 1;
        if (labels32[2 * (Bn * Tn / 2 - 1 - k) + 1] != 0) stride = 1;
    }

    float acc = 0.0f;
    const long long lbase = (long long)b * Tn;
    const long long fbase = (long long)b * Tn * Ln;
    for (int t = 1 + tid; t < Tn; t += 256) {
        int cur  = labels32[(lbase + t) * stride];
        int prev = labels32[(lbase + t - 1) * stride];
        acc += __ldg(trans + cur * Ln + prev) + __ldg(feats + fbase + t * Ln + cur);
    }

    #pragma unroll
    for (int off = 16; off; off >>= 1)
        acc += __shfl_xor_sync(0xffffffffu, acc, off);
    __shared__ float red[8];
    const int wid  = tid >> 5;
    const int lane = tid & 31;
    if (lane == 0) red[wid] = acc;
    __syncthreads();
    if (tid == 0) {
        float s = 0.0f;
        #pragma unroll
        for (int w = 0; w < 8; w++) s += red[w];
        g_gold[b] = s;
    }
}

// ============================================================================
// Forward algorithm. One block (64 threads) per batch; thread i owns label i.
// s_j = exp(a_j - M) broadcast via double-buffered smem; E row in 32 packed
// f32x2 registers; one barrier per step; depth-4 feats prefetch.
// R6 change vs R5 (198us forward, L1=70.5% = LDS-wavefront-bound):
//  - s read as ulonglong2 (LDS.128): 16 wavefronts/warp-step instead of 32,
//    and the 128-bit load lands directly in aligned reg pairs usable as
//    fma.rn.f32x2 operands -> no pack MOVs either.
// ============================================================================
__global__ __launch_bounds__(64, 8)
void crf_forward_kernel(const float* __restrict__ feats,
                        const float* __restrict__ trans,
                        float* __restrict__ out) {
    const int b = blockIdx.x;
    const int i = threadIdx.x;   // label 0..63

    __shared__ __align__(16) float sh_s[2][Ln];
    __shared__ float sh_delta[2];
    __shared__ float sh_red[2];

    // ---- E row i = exp(trans[i, :]) as 32 packed f32x2 registers ----
    unsigned long long E2[32];
    {
        const float2* trow = reinterpret_cast<const float2*>(trans + i * Ln);
        #pragma unroll
        for (int k = 0; k < 32; k++) {
            float2 tv = __ldg(trow + k);
            float e0 = (tv.x < -80.0f) ? 0.0f : __expf(tv.x);
            float e1 = (tv.y < -80.0f) ? 0.0f : __expf(tv.y);
            E2[k] = pk2(e0, e1);
        }
    }

    // ---- init: s one-hot at START, M = 0 ----
    sh_s[0][i] = (i == 0) ? 1.0f : 0.0f;
    if (i == 0) sh_delta[0] = 0.0f;
    float M = 0.0f;
    __syncthreads();

    const float* fp = feats + (long long)b * Tn * Ln + i;

    // ---- prefetch pipeline: step k consumes feat t=k+1; depth 4 ----
    float fb0 = __ldg(fp + 1 * Ln);
    float fb1 = __ldg(fp + 2 * Ln);
    float fb2 = __ldg(fp + 3 * Ln);
    float fb3 = __ldg(fp + 4 * Ln);

    float sn = 0.0f;

    // One forward step. CUR/NXT are compile-time 0/1. FB holds feat for this
    // step and is refilled with feat for t=TPF (clamped; redundant loads at
    // the tail are harmless and stay in-bounds).
    #define STEP(FB, CUR, NXT, TPF)                                          \
    {                                                                        \
        const float f_use = FB;                                              \
        const int tpf = ((TPF) < Tn) ? (TPF) : (Tn - 1);                     \
        FB = __ldg(fp + (long long)tpf * Ln);                                \
        const float delta = sh_delta[CUR];                                   \
        const ulonglong2* pv =                                               \
            reinterpret_cast<const ulonglong2*>(sh_s[CUR]);                  \
        unsigned long long a0 = 0ull, a1 = 0ull, a2 = 0ull, a3 = 0ull;       \
        _Pragma("unroll")                                                    \
        for (int k = 0; k < 16; k += 2) {                                    \
            ulonglong2 v0 = pv[k];                                           \
            ulonglong2 v1 = pv[k + 1];                                       \
            a0 = fma2(E2[2 * k + 0], v0.x, a0);                              \
            a1 = fma2(E2[2 * k + 1], v0.y, a1);                              \
            a2 = fma2(E2[2 * k + 2], v1.x, a2);                              \
            a3 = fma2(E2[2 * k + 3], v1.y, a3);                              \
        }                                                                    \
        unsigned long long asum = add2(add2(a0, a1), add2(a2, a3));          \
        float qlo, qhi;                                                      \
        unpk2(asum, qlo, qhi);                                               \
        const float q = qlo + qhi;                                           \
        sn = q * __expf(f_use - delta);                                      \
        M += delta;                                                          \
        if (i == 32) {                                                       \
            int e = ((__float_as_int(sn) >> 23) & 0xFF) - 127;               \
            e = (e < -43) ? -43 : ((e > 43) ? 43 : e);                       \
            sh_delta[NXT] = (float)e * LN2F;                                 \
        }                                                                    \
        sh_s[NXT][i] = sn;                                                   \
        __syncthreads();                                                     \
    }

    // 511 steps total: k = 0..510 (t = 1..511).
    // Main loop: 127 iterations x 4 steps = k 0..507.
    #pragma unroll 1
    for (int m = 0; m < 127; ++m) {
        const int k = 4 * m;
        STEP(fb0, 0, 1, k + 5);
        STEP(fb1, 1, 0, k + 6);
        STEP(fb2, 0, 1, k + 7);
        STEP(fb3, 1, 0, k + 8);
    }
    // Epilogue: k = 508, 509, 510.
    STEP(fb0, 0, 1, Tn - 1);
    STEP(fb1, 1, 0, Tn - 1);
    STEP(fb2, 0, 1, Tn - 1);

    #undef STEP

    // ---- log_Z = M + log(sum_i s_i);  out = log_Z - gold ----
    float v = sn;
    #pragma unroll
    for (int off = 16; off; off >>= 1)
        v += __shfl_xor_sync(0xffffffffu, v, off);
    if ((i & 31) == 0) sh_red[i >> 5] = v;
    __syncthreads();
    if (i == 0) {
        float total = sh_red[0] + sh_red[1];
        out[b] = M + logf(total) - g_gold[b];
    }
}

// ============================================================================
// Launch
// ============================================================================
extern "C" void kernel_launch(void* const* d_in, const int* in_sizes, int n_in,
                              void* d_out, int out_size) {
    const float* feats  = (const float*)d_in[0];   // [B, T, L] f32
    const float* trans  = (const float*)d_in[1];   // [L, L]    f32
    const int*   labels = (const int*)  d_in[2];   // [B, T]    int (32/64 detected)
    float* out = (float*)d_out;                    // [B] f32

    crf_gold_kernel<<<Bn, 256>>>(feats, trans, labels);
    crf_forward_kernel<<<Bn, Ln>>>(feats, trans, out);
}